// round 14
// baseline (speedup 1.0000x reference)
#include <cuda_runtime.h>
#include <cstdint>
#include <math.h>

#define EPSI 1e-5f

typedef unsigned long long u64t;

__device__ __forceinline__ u64t splat2(float a) {
    u64t r; asm("mov.b64 %0, {%1, %1};" : "=l"(r) : "f"(a)); return r;
}
__device__ __forceinline__ void fma2(u64t& d, u64t a, u64t b) {
    asm("fma.rn.f32x2 %0, %1, %2, %0;" : "+l"(d) : "l"(a), "l"(b));
}
__device__ __forceinline__ void unpack2(u64t v, float& lo, float& hi) {
    asm("mov.b64 {%0, %1}, %2;" : "=f"(lo), "=f"(hi) : "l"(v));
}
__device__ __forceinline__ void cp16(unsigned int dst, const void* src) {
    asm volatile("cp.async.cg.shared.global [%0], [%1], 16;" :: "r"(dst), "l"(src));
}

__device__ __forceinline__ float f4c(const float4& v, int i) {
    switch (i & 3) {
        case 0: return v.x;
        case 1: return v.y;
        case 2: return v.z;
        default: return v.w;
    }
}

#define XH_LD 132
#define SH_LD 132

// Full-width GEMM (accumulate-only): C[64 x 256] += A[64 x KTOT] * W[KTOT x 256].
// 256 threads, 8 warps; warp w owns cols [16w,+16) lo and [128+16w,+16) hi.
// Thread (rp=lane&3, q=lane>>2): 16 rows rp+4i (i<16), 4 contiguous cols
// (q<4: lo quad 16w+4q ; q>=4: hi quad 128+16w+4(q-4)). W smem k-row = 32
// floats [lo16|hi16]; one LDS.128 per k. A staged 4 rows at a time (regs).
// Per k per thread: 32 FFMA2, A 4 instr + W 1 instr. Warp-private W double
// buffer (8-k chunks) via own cp.async groups; NO __syncthreads inside.
template <int KTOT>
__device__ __forceinline__ void gemm_tile_acc(
    const float* __restrict__ As, int lda,
    const float* __restrict__ Wg, int ldw,
    float* __restrict__ wbuf, u64t (&acc)[16][2])
{
    const int tid  = threadIdx.x;
    const int wid  = tid >> 5, lane = tid & 31;
    const int rp   = lane & 3, q = lane >> 2;
    constexpr int NCH = KTOT / 8;

    float* wb = wbuf + wid * 512;
    const unsigned int wb_s = (unsigned int)__cvta_generic_to_shared(wb);
    const int part = lane & 3;
    const int seg0 = lane >> 2;   // 0..7

    auto load_chunk = [&](int ch, int stage) {
        const float* Wr = Wg + ch * 8 * ldw + wid * 16 + part * 4;
#pragma unroll
        for (int j = 0; j < 2; j++) {
            int seg = seg0 + 8 * j;          // 0..15
            int k = seg >> 1, half = seg & 1;
            cp16(wb_s + stage * 1024 + k * 128 + half * 64 + part * 16,
                 Wr + k * ldw + half * 128);
        }
        asm volatile("cp.async.commit_group;" ::: "memory");
    };

    load_chunk(0, 0);

    int cur = 0;
    for (int ch = 0; ch < NCH; ch++) {
        const bool more = (ch + 1 < NCH);
        if (more) {
            load_chunk(ch + 1, cur ^ 1);
            asm volatile("cp.async.wait_group 1;" ::: "memory");
        } else {
            asm volatile("cp.async.wait_group 0;" ::: "memory");
        }
        const float* wc = wb + cur * 256;
        const int kk = ch * 8;
#pragma unroll
        for (int k4 = 0; k4 < 2; k4++) {
            ulonglong2 wv[4];
#pragma unroll
            for (int kz = 0; kz < 4; kz++)
                wv[kz] = *reinterpret_cast<const ulonglong2*>(
                    wc + (k4 * 4 + kz) * 32 + q * 4);
#pragma unroll
            for (int qtr = 0; qtr < 4; qtr++) {
                float4 a[4];
#pragma unroll
                for (int i = 0; i < 4; i++)
                    a[i] = *reinterpret_cast<const float4*>(
                        As + (rp + 16 * qtr + 4 * i) * lda + kk + k4 * 4);
#pragma unroll
                for (int kz = 0; kz < 4; kz++) {
#pragma unroll
                    for (int i = 0; i < 4; i++) {
                        u64t s = splat2(f4c(a[i], kz));
                        fma2(acc[qtr * 4 + i][0], s, wv[kz].x);
                        fma2(acc[qtr * 4 + i][1], s, wv[kz].y);
                    }
                }
            }
        }
        cur ^= 1;
    }
}

// Half-width GEMM: live output cols {0..63} U {128..191} only.
// 8 warps = 2 row-groups (32 rows) x 4 col-groups. Thread: 8 rows x 4 cols.
template <int KTOT, typename Epi>
__device__ __forceinline__ void gemm_tile_half(
    const float* __restrict__ As, int lda,
    const float* __restrict__ Wg, int ldw,
    float* __restrict__ wbuf, Epi epi)
{
    const int tid  = threadIdx.x;
    const int wid  = tid >> 5, lane = tid & 31;
    const int w4   = wid & 3, grp = wid >> 2;
    const int rp   = lane & 3, q = lane >> 2;
    const int rbase = grp * 32 + rp;
    constexpr int NCH = KTOT / 8;

    float* wb = wbuf + wid * 512;
    const unsigned int wb_s = (unsigned int)__cvta_generic_to_shared(wb);
    const int part = lane & 3;
    const int seg0 = lane >> 2;

    u64t acc[8][2];
#pragma unroll
    for (int i = 0; i < 8; i++) { acc[i][0] = 0ull; acc[i][1] = 0ull; }

    auto load_chunk = [&](int ch, int stage) {
        const float* Wr = Wg + ch * 8 * ldw + w4 * 16 + part * 4;
#pragma unroll
        for (int j = 0; j < 2; j++) {
            int seg = seg0 + 8 * j;
            int k = seg >> 1, half = seg & 1;
            cp16(wb_s + stage * 1024 + k * 128 + half * 64 + part * 16,
                 Wr + k * ldw + half * 128);
        }
        asm volatile("cp.async.commit_group;" ::: "memory");
    };

    load_chunk(0, 0);

    int cur = 0;
    for (int ch = 0; ch < NCH; ch++) {
        const bool more = (ch + 1 < NCH);
        if (more) {
            load_chunk(ch + 1, cur ^ 1);
            asm volatile("cp.async.wait_group 1;" ::: "memory");
        } else {
            asm volatile("cp.async.wait_group 0;" ::: "memory");
        }
        const float* wc = wb + cur * 256;
        const int kk = ch * 8;
#pragma unroll
        for (int k4 = 0; k4 < 2; k4++) {
            ulonglong2 wv[4];
#pragma unroll
            for (int kz = 0; kz < 4; kz++)
                wv[kz] = *reinterpret_cast<const ulonglong2*>(
                    wc + (k4 * 4 + kz) * 32 + q * 4);
#pragma unroll
            for (int hg = 0; hg < 2; hg++) {
                float4 a[4];
#pragma unroll
                for (int i = 0; i < 4; i++)
                    a[i] = *reinterpret_cast<const float4*>(
                        As + (rbase + 16 * hg + 4 * i) * lda + kk + k4 * 4);
#pragma unroll
                for (int kz = 0; kz < 4; kz++) {
#pragma unroll
                    for (int i = 0; i < 4; i++) {
                        u64t s = splat2(f4c(a[i], kz));
                        fma2(acc[hg * 4 + i][0], s, wv[kz].x);
                        fma2(acc[hg * 4 + i][1], s, wv[kz].y);
                    }
                }
            }
        }
        cur ^= 1;
    }
    epi(rbase, acc);
}

__global__ __launch_bounds__(256, 2)
void tabnet_kernel(
    const float* __restrict__ x,
    const float* __restrict__ bn0_g, const float* __restrict__ bn0_b,
    const float* __restrict__ bn0_m, const float* __restrict__ bn0_v,
    const float* __restrict__ shW,
    const float* __restrict__ sh_g, const float* __restrict__ sh_b,
    const float* __restrict__ sh_m, const float* __restrict__ sh_v,
    const float* __restrict__ stW,
    const float* __restrict__ st_g, const float* __restrict__ st_b,
    const float* __restrict__ st_m, const float* __restrict__ st_v,
    const float* __restrict__ fW, const float* __restrict__ fb,
    float* __restrict__ out)
{
    extern __shared__ float smem[];
    float* xsh   = smem;             // [64][132] x K-quarter tile
    float* shb   = smem + 8448;      // [64][132] GLU(shared step) output
    float* aggs  = smem + 16896;     // [64][64]
    float* wbuf  = smem + 20992;     // 8 warps x 2 stages x 256
    float* bn0sc = smem + 25088;     // [512]
    float* bn0sh = smem + 25600;     // [512]
    float* sbnsc = smem + 26112;     // [256]
    float* sbnsh = smem + 26368;     // [256]
    // total 26624 floats = 106496 bytes -> 2 blocks/SM

    const int tid = threadIdx.x;
    const int row0 = blockIdx.x << 6;

    for (int c = tid; c < 512; c += 256) {
        float sc = bn0_g[c] * rsqrtf(bn0_v[c] + EPSI);
        bn0sc[c] = sc;
        bn0sh[c] = bn0_b[c] - bn0_m[c] * sc;
    }
    __syncthreads();

    // GEMM1 accumulators persist across the four K-quarters
    u64t acc1[16][2];
#pragma unroll
    for (int i = 0; i < 16; i++) { acc1[i][0] = 0ull; acc1[i][1] = 0ull; }

    for (int ph = 0; ph < 4; ph++) {
        if (ph) __syncthreads();   // all warps done reading previous x quarter
        // load x quarter ph (cols [128ph, +128)) + bn0
        {
            const float4* xg = reinterpret_cast<const float4*>(x)
                             + (size_t)row0 * 128 + ph * 32;
            const float4* s4 = reinterpret_cast<const float4*>(bn0sc) + ph * 32;
            const float4* b4 = reinterpret_cast<const float4*>(bn0sh) + ph * 32;
            float4* xs4 = reinterpret_cast<float4*>(xsh);
#pragma unroll
            for (int i = 0; i < 8; i++) {
                int f = tid + 256 * i;
                int r = f >> 5, c4 = f & 31;
                float4 v = xg[r * 128 + c4];
                float4 s = s4[c4], b = b4[c4];
                v.x = fmaf(v.x, s.x, b.x);
                v.y = fmaf(v.y, s.y, b.y);
                v.z = fmaf(v.z, s.z, b.z);
                v.w = fmaf(v.w, s.w, b.w);
                xs4[r * 33 + c4] = v;
            }
        }
        __syncthreads();
        gemm_tile_acc<128>(xsh, XH_LD, shW + ph * 128 * 256, 256, wbuf, acc1);
    }

    // shared-step bn tables, then GEMM1 epilogue
    {
        int c = tid;
        float sc = sh_g[c] * rsqrtf(sh_v[c] + EPSI);
        sbnsc[c] = sc;
        sbnsh[c] = sh_b[c] - sh_m[c] * sc;
    }
    __syncthreads();

    // GEMM1 epilogue: sh = GLU(bn(.)); GLU pairing via shfl_xor(16).
    {
        const int wid = tid >> 5, lane = tid & 31;
        const int rp = lane & 3, q = lane >> 2;
        const int c0b = wid * 16 + (q & 3) * 4;
        const bool hib = q >= 4;
#pragma unroll
        for (int i = 0; i < 16; i++) {
            int row = rp + 4 * i;
            float v[4], bv[4], ov[4];
            unpack2(acc1[i][0], v[0], v[1]);
            unpack2(acc1[i][1], v[2], v[3]);
#pragma unroll
            for (int t = 0; t < 4; t++) {
                int col = (hib ? 128 : 0) + c0b + t;
                bv[t] = fmaf(v[t], sbnsc[col], sbnsh[col]);
            }
#pragma unroll
            for (int t = 0; t < 4; t++)
                ov[t] = __shfl_xor_sync(0xffffffffu, bv[t], 16);
            // lo lanes store rows i<8, hi lanes store rows i>=8
            if ((i >= 8) == hib) {
                float4 g;
                float u0 = hib ? ov[0] : bv[0], w0 = hib ? bv[0] : ov[0];
                float u1 = hib ? ov[1] : bv[1], w1 = hib ? bv[1] : ov[1];
                float u2 = hib ? ov[2] : bv[2], w2 = hib ? bv[2] : ov[2];
                float u3 = hib ? ov[3] : bv[3], w3 = hib ? bv[3] : ov[3];
                g.x = u0 / (1.f + __expf(-w0));
                g.y = u1 / (1.f + __expf(-w1));
                g.z = u2 / (1.f + __expf(-w2));
                g.w = u3 / (1.f + __expf(-w3));
                *reinterpret_cast<float4*>(shb + row * SH_LD + c0b) = g;
            }
        }
    }
    __syncthreads();

    // agg in registers: thread owns 4 rows x 4 cols
    float agg[4][4];
#pragma unroll
    for (int j = 0; j < 4; j++)
#pragma unroll
        for (int t = 0; t < 4; t++) agg[j][t] = 0.f;

    for (int s = 0; s < 3; s++) {
        {
            int c = tid;
            float sc = st_g[s * 256 + c] * rsqrtf(st_v[s * 256 + c] + EPSI);
            sbnsc[c] = sc;
            sbnsh[c] = st_b[s * 256 + c] - st_m[s * 256 + c] * sc;
        }
        __syncthreads();
        // GEMM2 (half): h_d = GLU(bn(sh @ stW[s]))[:, :64]; agg += h_d
        gemm_tile_half<128>(shb, SH_LD, stW + s * 128 * 256, 256, wbuf,
            [&](int rb, u64t (&acc)[8][2]) {
                const int lane = tid & 31;
                const int q = lane >> 2;
                const int w4 = (tid >> 5) & 3;
                const int c0b = w4 * 16 + (q & 3) * 4;
                const bool hib = q >= 4;
#pragma unroll
                for (int i = 0; i < 8; i++) {
                    float v[4], bv[4], ov[4];
                    unpack2(acc[i][0], v[0], v[1]);
                    unpack2(acc[i][1], v[2], v[3]);
#pragma unroll
                    for (int t = 0; t < 4; t++) {
                        int col = (hib ? 128 : 0) + c0b + t;
                        bv[t] = fmaf(v[t], sbnsc[col], sbnsh[col]);
                    }
#pragma unroll
                    for (int t = 0; t < 4; t++)
                        ov[t] = __shfl_xor_sync(0xffffffffu, bv[t], 16);
                    // lo lanes own i<4 ; hi lanes own i>=4
                    if ((i >= 4) == hib) {
                        int j = hib ? (i - 4) : i;
#pragma unroll
                        for (int t = 0; t < 4; t++) {
                            float u = hib ? ov[t] : bv[t];
                            float w = hib ? bv[t] : ov[t];
                            agg[j][t] += u / (1.f + __expf(-w));
                        }
                    }
                }
            });
        __syncthreads();
    }

    // write agg registers to smem (lo: rows rb+4j; hi: rows rb+16+4j)
    {
        const int wid = tid >> 5, lane = tid & 31;
        const int w4 = wid & 3, grp = wid >> 2;
        const int rp = lane & 3, q = lane >> 2;
        const int c0b = w4 * 16 + (q & 3) * 4;
        const bool hib = q >= 4;
        const int rb = grp * 32 + rp + (hib ? 16 : 0);
#pragma unroll
        for (int j = 0; j < 4; j++) {
            float4 g = make_float4(agg[j][0], agg[j][1], agg[j][2], agg[j][3]);
            *reinterpret_cast<float4*>(aggs + (rb + 4 * j) * 64 + c0b) = g;
        }
    }
    __syncthreads();

    // final: out = agg @ fW + fb
    if (tid < 128) {
        int m = tid >> 1, o = tid & 1;
        float acc = fb[o];
#pragma unroll
        for (int j = 0; j < 64; j++) acc = fmaf(aggs[m * 64 + j], fW[j * 2 + o], acc);
        out[(size_t)(row0 + m) * 2 + o] = acc;
    }
}

extern "C" void kernel_launch(void* const* d_in, const int* in_sizes, int n_in,
                              void* d_out, int out_size)
{
    const float* x    = (const float*)d_in[0];
    const float* bn0g = (const float*)d_in[1];
    const float* bn0b = (const float*)d_in[2];
    const float* bn0m = (const float*)d_in[3];
    const float* bn0v = (const float*)d_in[4];
    const float* shW  = (const float*)d_in[5];
    const float* shg  = (const float*)d_in[6];
    const float* shbp = (const float*)d_in[7];
    const float* shm  = (const float*)d_in[8];
    const float* shv  = (const float*)d_in[9];
    const float* stW  = (const float*)d_in[10];
    const float* stg  = (const float*)d_in[11];
    const float* stb  = (const float*)d_in[12];
    const float* stm  = (const float*)d_in[13];
    const float* stv  = (const float*)d_in[14];
    const float* fW   = (const float*)d_in[20];
    const float* fb   = (const float*)d_in[21];

    int Btot = in_sizes[0] / 512;
    int grid = Btot / 64;
    size_t smem = 26624 * sizeof(float);
    cudaFuncSetAttribute(tabnet_kernel,
                         cudaFuncAttributeMaxDynamicSharedMemorySize, (int)smem);
    tabnet_kernel<<<grid, 256, smem>>>(
        x, bn0g, bn0b, bn0m, bn0v,
        shW, shg, shbp, shm, shv,
        stW, stg, stb, stm, stv,
        fW, fb, (float*)d_out);
}

// round 16
// speedup vs baseline: 1.3600x; 1.3600x over previous
#include <cuda_runtime.h>
#include <cuda_fp16.h>
#include <cstdint>
#include <math.h>

#define EPSI 1e-5f
typedef unsigned long long u64t;
typedef unsigned int u32;

// shW pre-split fp16 hi/lo, stored in exact B-fragment register order:
// index = ((st*8 + w)*32 + lane)*8 + nt*2 + r   (st = k16-step 0..31)
__device__ u32 g_Bh[65536];
__device__ u32 g_Bl[65536];

// ---- validated helpers ----
__device__ __forceinline__ u64t splat2(float a) {
    u64t r; asm("mov.b64 %0, {%1, %1};" : "=l"(r) : "f"(a)); return r;
}
__device__ __forceinline__ void fma2(u64t& d, u64t a, u64t b) {
    asm("fma.rn.f32x2 %0, %1, %2, %0;" : "+l"(d) : "l"(a), "l"(b));
}
__device__ __forceinline__ void unpack2(u64t v, float& lo, float& hi) {
    asm("mov.b64 {%0, %1}, %2;" : "=f"(lo), "=f"(hi) : "l"(v));
}
__device__ __forceinline__ void cp16(u32 dst, const void* src) {
    asm volatile("cp.async.cg.shared.global [%0], [%1], 16;" :: "r"(dst), "l"(src));
}
__device__ __forceinline__ float f4c(const float4& v, int i) {
    switch (i & 3) {
        case 0: return v.x;
        case 1: return v.y;
        case 2: return v.z;
        default: return v.w;
    }
}
__device__ __forceinline__ u32 smem_u32(const void* p) {
    return (u32)__cvta_generic_to_shared(p);
}

// warp-level HMMA m16n8k16 fp16 -> fp32 accumulate (baseline PTX, sm_80+)
__device__ __forceinline__ void mma16816(float* d, const u32* a, const u32* b) {
    asm volatile(
        "mma.sync.aligned.m16n8k16.row.col.f32.f16.f16.f32 "
        "{%0,%1,%2,%3}, {%4,%5,%6,%7}, {%8,%9}, {%0,%1,%2,%3};"
        : "+f"(d[0]), "+f"(d[1]), "+f"(d[2]), "+f"(d[3])
        : "r"(a[0]), "r"(a[1]), "r"(a[2]), "r"(a[3]), "r"(b[0]), "r"(b[1]));
}

// ---- prep: split shW[512][256] -> fp16 hi/lo B fragments ----
__global__ void prep_kernel(const float* __restrict__ shW) {
    int idx = blockIdx.x * 256 + threadIdx.x;   // 65536
    int r    = idx & 1;
    int nt   = (idx >> 1) & 3;
    int lane = (idx >> 3) & 31;
    int w    = (idx >> 8) & 7;
    int st   = idx >> 11;
    int k   = st * 16 + (lane & 3) * 2 + (r ? 8 : 0);
    int col = w * 32 + nt * 8 + (lane >> 2);
    float v0 = shW[k * 256 + col];
    float v1 = shW[(k + 1) * 256 + col];
    __half h0 = __float2half_rn(v0), h1 = __float2half_rn(v1);
    __half l0 = __float2half_rn(v0 - __half2float(h0));
    __half l1 = __float2half_rn(v1 - __half2float(h1));
    g_Bh[idx] = (u32)__half_as_ushort(h0) | ((u32)__half_as_ushort(h1) << 16);
    g_Bl[idx] = (u32)__half_as_ushort(l0) | ((u32)__half_as_ushort(l1) << 16);
}

#define SH_LD 132

// ---- R12-validated FFMA2 half-GEMM (GEMM2), unchanged ----
template <int KTOT, typename Epi>
__device__ __forceinline__ void gemm_tile_half(
    const float* __restrict__ As, int lda,
    const float* __restrict__ Wg, int ldw,
    float* __restrict__ wbuf, Epi epi)
{
    const int tid  = threadIdx.x;
    const int wid  = tid >> 5, lane = tid & 31;
    const int w4   = wid & 3, grp = wid >> 2;
    const int rp   = lane & 3, q = lane >> 2;
    const int rbase = grp * 16 + rp;
    constexpr int NCH = KTOT / 16;

    float* wb = wbuf + wid * 1024;
    const u32 wb_s = smem_u32(wb);
    const int seg0 = lane >> 2;
    const int part = lane & 3;

    u64t acc[4][2];
#pragma unroll
    for (int i = 0; i < 4; i++) { acc[i][0] = 0ull; acc[i][1] = 0ull; }

    auto load_chunk = [&](int ch, int stage) {
        const float* Wr = Wg + ch * 16 * ldw + w4 * 16 + part * 4;
#pragma unroll
        for (int j = 0; j < 4; j++) {
            int seg = seg0 + 8 * j;
            int k = seg >> 1, half = seg & 1;
            cp16(wb_s + stage * 2048 + k * 128 + half * 64 + part * 16,
                 Wr + k * ldw + half * 128);
        }
        asm volatile("cp.async.commit_group;" ::: "memory");
    };

    load_chunk(0, 0);

    int cur = 0;
    for (int ch = 0; ch < NCH; ch++) {
        const bool more = (ch + 1 < NCH);
        if (more) {
            load_chunk(ch + 1, cur ^ 1);
            asm volatile("cp.async.wait_group 1;" ::: "memory");
        } else {
            asm volatile("cp.async.wait_group 0;" ::: "memory");
        }
        const float* wc = wb + cur * 512;
        const int kk = ch * 16;
#pragma unroll
        for (int k4 = 0; k4 < 4; k4++) {
            float4 a[4];
#pragma unroll
            for (int i = 0; i < 4; i++)
                a[i] = *reinterpret_cast<const float4*>(
                    As + (rbase + 4 * i) * lda + kk + k4 * 4);
#pragma unroll
            for (int kz = 0; kz < 4; kz++) {
                ulonglong2 wv = *reinterpret_cast<const ulonglong2*>(
                    wc + (k4 * 4 + kz) * 32 + q * 4);
#pragma unroll
                for (int i = 0; i < 4; i++) {
                    u64t s = splat2(f4c(a[i], kz));
                    fma2(acc[i][0], s, wv.x);
                    fma2(acc[i][1], s, wv.y);
                }
            }
        }
        cur ^= 1;
    }
    epi(rbase, acc);
}

__global__ __launch_bounds__(256, 2)
void tabnet_kernel(
    const float* __restrict__ x,
    const float* __restrict__ bn0_g, const float* __restrict__ bn0_b,
    const float* __restrict__ bn0_m, const float* __restrict__ bn0_v,
    const float* __restrict__ sh_g, const float* __restrict__ sh_b,
    const float* __restrict__ sh_m, const float* __restrict__ sh_v,
    const float* __restrict__ stW,
    const float* __restrict__ st_g, const float* __restrict__ st_b,
    const float* __restrict__ st_m, const float* __restrict__ st_v,
    const float* __restrict__ fW, const float* __restrict__ fb,
    float* __restrict__ out)
{
    extern __shared__ float smem[];
    float* shb   = smem;             // [32][132] = 4224
    float* aggs  = smem + 4224;      // [32][64]  = 2048
    float* buf0  = smem + 6272;      // 9216: GEMM1 A/B frags -> zs -> GEMM2 wbuf
    float* bn0sc = smem + 15488;     // 512
    float* bn0sh = smem + 16000;     // 512
    float* sbnsc = smem + 16512;     // 256
    float* sbnsh = smem + 16768;     // 256
    // total 17024 floats = 68096 bytes -> 2 blocks/SM

    const int tid = threadIdx.x;
    const int wid = tid >> 5, lane = tid & 31;
    const int row0 = blockIdx.x << 5;

    for (int c = tid; c < 512; c += 256) {
        float sc = bn0_g[c] * rsqrtf(bn0_v[c] + EPSI);
        bn0sc[c] = sc;
        bn0sh[c] = bn0_b[c] - bn0_m[c] * sc;
    }
    {
        int c = tid;
        float sc = sh_g[c] * rsqrtf(sh_v[c] + EPSI);
        sbnsc[c] = sc;
        sbnsh[c] = sh_b[c] - sh_m[c] * sc;
    }
    __syncthreads();

    u32* Ah = reinterpret_cast<u32*>(buf0);  // 512 u32
    u32* Al = Ah + 512;                      // 512
    u32* Bh = Al + 512;                      // 4096
    u32* Bl = Bh + 4096;                     // 4096
    const u32 sBh = smem_u32(Bh), sBl = smem_u32(Bl);

    float c_[2][4][4];
#pragma unroll
    for (int mt = 0; mt < 2; mt++)
#pragma unroll
        for (int nt = 0; nt < 4; nt++)
#pragma unroll
            for (int t = 0; t < 4; t++) c_[mt][nt][t] = 0.f;

    // ---- GEMM1: 16 chunks of 32 k (2 k16-steps each) ----
    for (int ch = 0; ch < 16; ch++) {
        if (ch) __syncthreads();     // previous chunk's frags consumed
        // B chunk (pre-packed): straight cp.async, 16KB per term
        {
            const char* srcH = (const char*)g_Bh + (size_t)ch * 16384;
            const char* srcL = (const char*)g_Bl + (size_t)ch * 16384;
#pragma unroll
            for (int i = 0; i < 4; i++) {
                int off = (tid + 256 * i) * 16;
                cp16(sBh + off, srcH + off);
                cp16(sBl + off, srcL + off);
            }
            asm volatile("cp.async.commit_group;" ::: "memory");
        }
        // A chunk: x cols [32ch,+32) -> bn0 -> fp16 hi/lo -> fragment layout
#pragma unroll
        for (int pp = 0; pp < 2; pp++) {
            int p = tid + 256 * pp;            // 0..511 (row, kpair)
            int row = p >> 4, kp = p & 15;
            int kl = kp * 2;
            int gc = ch * 32 + kl;
            float2 v2 = *reinterpret_cast<const float2*>(
                x + (size_t)(row0 + row) * 512 + gc);
            float v0 = fmaf(v2.x, bn0sc[gc], bn0sh[gc]);
            float v1 = fmaf(v2.y, bn0sc[gc + 1], bn0sh[gc + 1]);
            __half h0 = __float2half_rn(v0), h1 = __float2half_rn(v1);
            __half l0 = __float2half_rn(v0 - __half2float(h0));
            __half l1 = __float2half_rn(v1 - __half2float(h1));
            int s = kl >> 4, kc = kl & 15;
            int chalf = kc >> 3;
            int mt = row >> 4, r16 = row & 15;
            int r = chalf * 2 + (r16 >> 3);
            int ln = (r16 & 7) * 4 + ((kc & 7) >> 1);
            int dst = ((s * 2 + mt) * 32 + ln) * 4 + r;
            Ah[dst] = (u32)__half_as_ushort(h0) | ((u32)__half_as_ushort(h1) << 16);
            Al[dst] = (u32)__half_as_ushort(l0) | ((u32)__half_as_ushort(l1) << 16);
        }
        asm volatile("cp.async.wait_group 0;" ::: "memory");
        __syncthreads();

#pragma unroll
        for (int s = 0; s < 2; s++) {
            u32 ah[2][4], al[2][4];
#pragma unroll
            for (int mt = 0; mt < 2; mt++) {
                uint4 t  = *reinterpret_cast<const uint4*>(Ah + ((s * 2 + mt) * 32 + lane) * 4);
                ah[mt][0] = t.x; ah[mt][1] = t.y; ah[mt][2] = t.z; ah[mt][3] = t.w;
                uint4 t2 = *reinterpret_cast<const uint4*>(Al + ((s * 2 + mt) * 32 + lane) * 4);
                al[mt][0] = t2.x; al[mt][1] = t2.y; al[mt][2] = t2.z; al[mt][3] = t2.w;
            }
            u32 bh[8], bl[8];
            {
                const uint4* bp = reinterpret_cast<const uint4*>(Bh + ((s * 8 + wid) * 32 + lane) * 8);
                uint4 b0 = bp[0], b1 = bp[1];
                bh[0] = b0.x; bh[1] = b0.y; bh[2] = b0.z; bh[3] = b0.w;
                bh[4] = b1.x; bh[5] = b1.y; bh[6] = b1.z; bh[7] = b1.w;
                const uint4* bq = reinterpret_cast<const uint4*>(Bl + ((s * 8 + wid) * 32 + lane) * 8);
                uint4 c0 = bq[0], c1 = bq[1];
                bl[0] = c0.x; bl[1] = c0.y; bl[2] = c0.z; bl[3] = c0.w;
                bl[4] = c1.x; bl[5] = c1.y; bl[6] = c1.z; bl[7] = c1.w;
            }
#pragma unroll
            for (int nt = 0; nt < 4; nt++) {
#pragma unroll
                for (int mt = 0; mt < 2; mt++) {
                    mma16816(c_[mt][nt], ah[mt], &bh[nt * 2]);
                    mma16816(c_[mt][nt], ah[mt], &bl[nt * 2]);
                    mma16816(c_[mt][nt], al[mt], &bh[nt * 2]);
                }
            }
        }
    }
    __syncthreads();   // frag buffers free -> reuse as zs

    // ---- GEMM1 epilogue: bn -> zs, then GLU -> shb ----
    float* zs = buf0;  // [32][260]
    {
#pragma unroll
        for (int mt = 0; mt < 2; mt++)
#pragma unroll
            for (int nt = 0; nt < 4; nt++) {
                int colb = wid * 32 + nt * 8 + (lane & 3) * 2;
                int rl = mt * 16 + (lane >> 2);
                float z0 = fmaf(c_[mt][nt][0], sbnsc[colb],     sbnsh[colb]);
                float z1 = fmaf(c_[mt][nt][1], sbnsc[colb + 1], sbnsh[colb + 1]);
                float z2 = fmaf(c_[mt][nt][2], sbnsc[colb],     sbnsh[colb]);
                float z3 = fmaf(c_[mt][nt][3], sbnsc[colb + 1], sbnsh[colb + 1]);
                *reinterpret_cast<float2*>(zs + rl * 260 + colb)       = make_float2(z0, z1);
                *reinterpret_cast<float2*>(zs + (rl + 8) * 260 + colb) = make_float2(z2, z3);
            }
    }
    __syncthreads();
#pragma unroll
    for (int i = 0; i < 16; i++) {
        int idx = tid + 256 * i;    // 4096
        int rr = idx >> 7, cc = idx & 127;
        float u  = zs[rr * 260 + cc];
        float wv = zs[rr * 260 + cc + 128];
        shb[rr * SH_LD + cc] = u / (1.f + __expf(-wv));
    }
    __syncthreads();

    // ---- GEMM2 (FFMA2, R12) ----
    float agg[2][4];
#pragma unroll
    for (int j = 0; j < 2; j++)
#pragma unroll
        for (int t = 0; t < 4; t++) agg[j][t] = 0.f;

    for (int s = 0; s < 3; s++) {
        {
            int c = tid;
            float sc = st_g[s * 256 + c] * rsqrtf(st_v[s * 256 + c] + EPSI);
            sbnsc[c] = sc;
            sbnsh[c] = st_b[s * 256 + c] - st_m[s * 256 + c] * sc;
        }
        __syncthreads();
        gemm_tile_half<128>(shb, SH_LD, stW + s * 128 * 256, 256, buf0,
            [&](int rb, u64t (&acc)[4][2]) {
                const int lane2 = tid & 31;
                const int q = lane2 >> 2;
                const int w4 = (tid >> 5) & 3;
                const int c0b = w4 * 16 + (q & 3) * 4;
                const bool hib = q >= 4;
#pragma unroll
                for (int i = 0; i < 4; i++) {
                    float v[4], bv[4], ov[4];
                    unpack2(acc[i][0], v[0], v[1]);
                    unpack2(acc[i][1], v[2], v[3]);
#pragma unroll
                    for (int t = 0; t < 4; t++) {
                        int col = (hib ? 128 : 0) + c0b + t;
                        bv[t] = fmaf(v[t], sbnsc[col], sbnsh[col]);
                    }
#pragma unroll
                    for (int t = 0; t < 4; t++)
                        ov[t] = __shfl_xor_sync(0xffffffffu, bv[t], 16);
                    if ((i >= 2) == hib) {
                        int j = hib ? (i - 2) : i;
#pragma unroll
                        for (int t = 0; t < 4; t++) {
                            float u = hib ? ov[t] : bv[t];
                            float w = hib ? bv[t] : ov[t];
                            agg[j][t] += u / (1.f + __expf(-w));
                        }
                    }
                }
            });
        __syncthreads();
    }

    // write agg (lo lanes: rows rb+{0,4}; hi: rb+{8,12})
    {
        const int w4 = wid & 3, grp = wid >> 2;
        const int rp = lane & 3, q = lane >> 2;
        const int c0b = w4 * 16 + (q & 3) * 4;
        const bool hib = q >= 4;
        const int rb = grp * 16 + rp + (hib ? 8 : 0);
#pragma unroll
        for (int j = 0; j < 2; j++) {
            float4 g = make_float4(agg[j][0], agg[j][1], agg[j][2], agg[j][3]);
            *reinterpret_cast<float4*>(aggs + (rb + 4 * j) * 64 + c0b) = g;
        }
    }
    __syncthreads();

    // final: out = agg @ fW + fb
    if (tid < 64) {
        int m = tid >> 1, o = tid & 1;
        float acc = fb[o];
#pragma unroll
        for (int j = 0; j < 64; j++) acc = fmaf(aggs[m * 64 + j], fW[j * 2 + o], acc);
        out[(size_t)(row0 + m) * 2 + o] = acc;
    }
}

extern "C" void kernel_launch(void* const* d_in, const int* in_sizes, int n_in,
                              void* d_out, int out_size)
{
    const float* x    = (const float*)d_in[0];
    const float* bn0g = (const float*)d_in[1];
    const float* bn0b = (const float*)d_in[2];
    const float* bn0m = (const float*)d_in[3];
    const float* bn0v = (const float*)d_in[4];
    const float* shW  = (const float*)d_in[5];
    const float* shg  = (const float*)d_in[6];
    const float* shbp = (const float*)d_in[7];
    const float* shm  = (const float*)d_in[8];
    const float* shv  = (const float*)d_in[9];
    const float* stW  = (const float*)d_in[10];
    const float* stg  = (const float*)d_in[11];
    const float* stb  = (const float*)d_in[12];
    const float* stm  = (const float*)d_in[13];
    const float* stv  = (const float*)d_in[14];
    const float* fW   = (const float*)d_in[20];
    const float* fb   = (const float*)d_in[21];

    prep_kernel<<<256, 256>>>(shW);

    int Btot = in_sizes[0] / 512;
    int grid = Btot / 32;
    size_t smem = 17024 * sizeof(float);
    cudaFuncSetAttribute(tabnet_kernel,
                         cudaFuncAttributeMaxDynamicSharedMemorySize, (int)smem);
    tabnet_kernel<<<grid, 256, smem>>>(
        x, bn0g, bn0b, bn0m, bn0v,
        shg, shbp, shm, shv,
        stW, stg, stb, stm, stv,
        fW, fb, (float*)d_out);
}